// round 13
// baseline (speedup 1.0000x reference)
#include <cuda_runtime.h>

// N-body all-pairs gravity, fp32. FP32-datapath bound (R5 f32x2 experiment:
// half the issues, same time). This round cuts fma-pipe ops 12 -> 10 per
// interaction via (a) dot-form d^2 with precomputed -2*p_i and |p|^2 terms,
// (b) moment-form accumulation f_i = S1 - p_i*S0 (no per-pair diff vector),
// (c) wm = (m*rcp(d2))*rsqrt(d2): 2 FMUL + 2 single-op MUFUs.
// Only rsqrt.approx / rcp.approx used (lg2/ex2 proved to expand multi-op).

constexpr int NBODY   = 8192;
constexpr int BLOCK   = 256;
constexpr int IBLK    = 4;
constexpr int ISTRIDE = NBODY / IBLK;         // 2048
constexpr int NSPLIT  = 128;                  // j-dimension splits
constexpr int CHUNK   = NBODY / NSPLIT;       // 64 j-bodies per tile

constexpr float EPS2 = 1e-4f;                 // softening^2

__device__ __forceinline__ float rcp_approx(float x) {
    float r; asm("rcp.approx.f32 %0, %1;" : "=f"(r) : "f"(x)); return r;  // MUFU.RCP
}

__global__ __launch_bounds__(BLOCK)
void nbody_kernel(const float* __restrict__ pos,
                  const float* __restrict__ mass,
                  float* __restrict__ out)
{
    __shared__ float4 sh[CHUNK];    // (x, y, z, q = |p|^2 + eps^2)
    __shared__ float  shm[CHUNK];   // m

    const int i0    = blockIdx.x * BLOCK + threadIdx.x;   // [0, 2048)
    const int jBase = blockIdx.y * CHUNK;

    if (threadIdx.x < CHUNK) {
        const int j = jBase + threadIdx.x;
        const float x = pos[3 * j + 0];
        const float y = pos[3 * j + 1];
        const float z = pos[3 * j + 2];
        const float q = fmaf(x, x, fmaf(y, y, fmaf(z, z, EPS2)));
        sh[threadIdx.x]  = make_float4(x, y, z, q);
        shm[threadIdx.x] = mass[j];
    }
    __syncthreads();

    float px[IBLK], py[IBLK], pz[IBLK];     // p_i
    float cx[IBLK], cy[IBLK], cz[IBLK];     // -2*p_i
    float qi[IBLK];                         // |p_i|^2
    float s0[IBLK], s1x[IBLK], s1y[IBLK], s1z[IBLK];
#pragma unroll
    for (int k = 0; k < IBLK; ++k) {
        const int i = i0 + k * ISTRIDE;
        px[k] = pos[3 * i + 0];
        py[k] = pos[3 * i + 1];
        pz[k] = pos[3 * i + 2];
        cx[k] = -2.0f * px[k];
        cy[k] = -2.0f * py[k];
        cz[k] = -2.0f * pz[k];
        qi[k] = fmaf(px[k], px[k], fmaf(py[k], py[k], pz[k] * pz[k]));
        s0[k] = 0.f; s1x[k] = 0.f; s1y[k] = 0.f; s1z[k] = 0.f;
    }

#pragma unroll 8
    for (int t = 0; t < CHUNK; ++t) {
        const float4 b  = sh[t];             // one LDS.128 serves 4 i-bodies
        const float  mj = shm[t];
#pragma unroll
        for (int k = 0; k < IBLK; ++k) {     // 4 independent chains
            // d2 = |pi|^2 + |pj|^2 + eps^2 - 2*pi.pj   (3 FFMA + 1 FADD)
            const float u  = fmaf(cx[k], b.x, fmaf(cy[k], b.y, fmaf(cz[k], b.z, qi[k])));
            const float d2 = u + b.w;
            // wm = m * d2^-1.5 = (m*rcp(d2)) * rsqrt(d2)   (2 FMUL + 2 MUFU)
            const float rc = rcp_approx(d2);
            const float rs = rsqrtf(d2);
            const float wm = (mj * rc) * rs;
            // moment accumulation (1 FADD + 3 FFMA)
            s0[k]  += wm;
            s1x[k]  = fmaf(wm, b.x, s1x[k]);
            s1y[k]  = fmaf(wm, b.y, s1y[k]);
            s1z[k]  = fmaf(wm, b.z, s1z[k]);
        }
    }

#pragma unroll
    for (int k = 0; k < IBLK; ++k) {
        const int i = i0 + k * ISTRIDE;
        // f_i = S1 - p_i * S0
        atomicAdd(&out[3 * i + 0], fmaf(-px[k], s0[k], s1x[k]));
        atomicAdd(&out[3 * i + 1], fmaf(-py[k], s0[k], s1y[k]));
        atomicAdd(&out[3 * i + 2], fmaf(-pz[k], s0[k], s1z[k]));
    }
}

extern "C" void kernel_launch(void* const* d_in, const int* in_sizes, int n_in,
                              void* d_out, int out_size)
{
    const float* pos  = (const float*)d_in[0];   // [8192, 3] fp32
    const float* mass = (const float*)d_in[1];   // [8192]    fp32
    float*       out  = (float*)d_out;           // [8192, 3] fp32

    cudaMemsetAsync(out, 0, (size_t)out_size * sizeof(float));

    dim3 grid(ISTRIDE / BLOCK, NSPLIT);          // 8 x 128 = 1024 CTAs
    nbody_kernel<<<grid, BLOCK>>>(pos, mass, out);
}